// round 2
// baseline (speedup 1.0000x reference)
#include <cuda_runtime.h>

#define BATCH 4096
#define NN 64
#define HH 16
#define FALLBACK_SIZE 12

__device__ float    g_partials[BATCH];
__device__ unsigned g_count = 0;

__global__ __launch_bounds__(256) void energy_kernel(
    const float* __restrict__ grid,   // [B,1,64,64]
    const float* __restrict__ hints,  // [B,2,64,16]
    const float* __restrict__ wg,     // [1,64,64]
    const float* __restrict__ wh,     // [2,64,16]
    float* __restrict__ out)
{
    __shared__ float s_row_target[NN];
    __shared__ float s_col_target[NN];
    __shared__ float s_colpart[8 * NN];
    __shared__ float s_warp[8];
    __shared__ int   s_last_rc[2];
    __shared__ bool  s_is_last;
    __shared__ double s_dwarp[8];

    const int b = blockIdx.x;
    const int t = threadIdx.x;
    const int lane = t & 31;
    const int wid  = t >> 5;

    const float* gb = grid  + (size_t)b * (NN * NN);
    const float* hb = hints + (size_t)b * (2 * NN * HH);

    // thread t -> row i = t/4, column group cg = t%4 (16 contiguous cols)
    const int i  = t >> 2;
    const int cg = t & 3;

    // ---- Prefetch grid + w_g (independent of size) so DRAM latency overlaps
    //      with the hints phase and the two barriers below. ----
    const float4* gp  = (const float4*)(gb + i * NN + cg * 16);
    const float4* wgp = (const float4*)(wg + i * NN + cg * 16);
    float4 g4[4], w4[4];
    #pragma unroll
    for (int q = 0; q < 4; q++) { g4[q] = gp[q]; w4[q] = wgp[q]; }

    float neural = 0.f;

    // ---- Phase 1: hints -> targets + neural(hints . w_h) ----
    if (t < 128) {
        const int k = t >> 6;      // 0 = row hints, 1 = col hints
        const int r = t & 63;
        const float4* hp = (const float4*)(hb + k * (NN * HH) + r * HH);
        const float4* wp = (const float4*)(wh + k * (NN * HH) + r * HH);
        float tsum = 0.f;
        #pragma unroll
        for (int q = 0; q < 4; q++) {
            float4 h4 = hp[q];
            float4 whv = wp[q];
            tsum   += h4.x + h4.y + h4.z + h4.w;
            neural += h4.x * whv.x + h4.y * whv.y + h4.z * whv.z + h4.w * whv.w;
        }
        if (k == 0) s_row_target[r] = tsum;
        else        s_col_target[r] = tsum;
    }
    __syncthreads();

    // ---- Phase 2: puzzle size — parallel max-index scan in warps 0,1 ----
    if (wid < 2) {
        const float* tgt = (wid == 0) ? s_row_target : s_col_target;
        int v0 = (tgt[lane]      > 0.f) ? lane      : -1;
        int v1 = (tgt[lane + 32] > 0.f) ? lane + 32 : -1;
        int v = max(v0, v1);
        #pragma unroll
        for (int off = 16; off > 0; off >>= 1)
            v = max(v, __shfl_xor_sync(0xffffffffu, v, off));
        if (lane == 0) s_last_rc[wid] = v;
    }
    __syncthreads();
    const int last_r = s_last_rc[0], last_c = s_last_rc[1];
    const int size = (last_r >= 0 && last_c >= 0) ? (max(last_r, last_c) + 1)
                                                  : FALLBACK_SIZE;
    const float sz = (float)size;

    // ---- Phase 3: grid pass (data already in registers) ----
    const bool rin = (i < size);
    const float rmask = rin ? 1.f : 0.f;

    float csg[16];
    float rowacc = 0.f;
    float binsum = 0.f;

    #pragma unroll
    for (int q = 0; q < 4; q++) {
        float gs[4] = {g4[q].x, g4[q].y, g4[q].z, g4[q].w};
        float ws[4] = {w4[q].x, w4[q].y, w4[q].z, w4[q].w};
        #pragma unroll
        for (int e = 0; e < 4; e++) {
            const int j = cg * 16 + q * 4 + e;
            const float g = gs[e];
            neural += g * ws[e];
            const float s = __fdividef(1.f, 1.f + __expf(-3.f * g));
            const float jmask = (j < size) ? 1.f : 0.f;
            rowacc += s * jmask;
            binsum += g * g * jmask * rmask;
            csg[q * 4 + e] = s * rmask;
        }
    }

    // actual_rows[i]: reduce across the 4 column-group lanes
    rowacc += __shfl_xor_sync(0xffffffffu, rowacc, 1);
    rowacc += __shfl_xor_sync(0xffffffffu, rowacc, 2);

    float rowerr = 0.f;
    if (cg == 0 && rin) {
        const float d = rowacc - s_row_target[i];
        rowerr = d * d;
    }

    // actual_cols: reduce csg over the 8 rows in this warp (lane = (i%8)*4 + cg)
    #pragma unroll
    for (int x = 0; x < 16; x++) {
        csg[x] += __shfl_xor_sync(0xffffffffu, csg[x], 4);
        csg[x] += __shfl_xor_sync(0xffffffffu, csg[x], 8);
        csg[x] += __shfl_xor_sync(0xffffffffu, csg[x], 16);
    }
    if (lane < 4) {
        #pragma unroll
        for (int x = 0; x < 16; x++)
            s_colpart[wid * NN + lane * 16 + x] = csg[x];
    }
    __syncthreads();

    float colerr = 0.f;
    if (t < NN && t < size) {
        float csum = 0.f;
        #pragma unroll
        for (int w = 0; w < 8; w++) csum += s_colpart[w * NN + t];
        const float d = csum - s_col_target[t];
        colerr = d * d;
    }

    float v = neural
            + (10.f / sz) * (rowerr + colerr)
            + (0.1f / (sz * sz)) * binsum;

    // ---- Block reduction -> per-block partial ----
    #pragma unroll
    for (int off = 16; off > 0; off >>= 1)
        v += __shfl_xor_sync(0xffffffffu, v, off);
    if (lane == 0) s_warp[wid] = v;
    __syncthreads();
    if (t == 0) {
        float p = 0.f;
        #pragma unroll
        for (int w = 0; w < 8; w++) p += s_warp[w];
        g_partials[b] = p;
        __threadfence();
        unsigned old = atomicInc(&g_count, BATCH - 1);   // wraps to 0 -> replay-safe
        s_is_last = (old == BATCH - 1);
    }
    __syncthreads();

    // ---- Last block performs the final reduction ----
    if (s_is_last) {
        double acc = 0.0;
        #pragma unroll
        for (int q = 0; q < BATCH / 256; q++)
            acc += (double)g_partials[t + q * 256];
        #pragma unroll
        for (int off = 16; off > 0; off >>= 1)
            acc += __shfl_xor_sync(0xffffffffu, acc, off);
        if (lane == 0) s_dwarp[wid] = acc;
        __syncthreads();
        if (t < 8) {
            acc = s_dwarp[t];
            acc += __shfl_xor_sync(0xffu, acc, 4);
            acc += __shfl_xor_sync(0xffu, acc, 2);
            acc += __shfl_xor_sync(0xffu, acc, 1);
            if (t == 0) out[0] = (float)(acc * (1.0 / (double)BATCH));
        }
    }
}

extern "C" void kernel_launch(void* const* d_in, const int* in_sizes, int n_in,
                              void* d_out, int out_size) {
    const float* grid  = (const float*)d_in[0];
    const float* hints = (const float*)d_in[1];
    const float* wg    = (const float*)d_in[2];
    const float* wh    = (const float*)d_in[3];
    float* out = (float*)d_out;

    energy_kernel<<<BATCH, 256>>>(grid, hints, wg, wh, out);
}